// round 1
// baseline (speedup 1.0000x reference)
#include <cuda_runtime.h>
#include <cstdint>

#define FEAT 128
#define HID  64
#define NMAX 100000

// Scratch (device globals — no runtime allocation allowed)
__device__ float g_h1[NMAX * HID];   // x@W1+b1
__device__ float g_a1[NMAX * HID];   // spmm1 output
__device__ float g_h3[NMAX * HID];   // (relu(a1)*mask)@W2+b2
__device__ float g_a2[NMAX * HID];   // spmm2 output (only kept rows valid)
__device__ unsigned char g_keep[NMAX];

// ---------------------------------------------------------------------------
// Reset: zero a1 fully, zero keep flags
// ---------------------------------------------------------------------------
__global__ void k_reset(int n) {
    int tid = blockIdx.x * blockDim.x + threadIdx.x;
    int stride = gridDim.x * blockDim.x;
    int total4 = n * HID / 4;
    float4 z = make_float4(0.f, 0.f, 0.f, 0.f);
    for (int t = tid; t < total4; t += stride)
        reinterpret_cast<float4*>(g_a1)[t] = z;
    for (int t = tid; t < n; t += stride)
        g_keep[t] = 0;
}

// ---------------------------------------------------------------------------
// Mark needed output rows and zero their a2 rows (duplicates race benignly)
// ---------------------------------------------------------------------------
__global__ void k_mark(const int* __restrict__ idx, int nidx) {
    int i = blockIdx.x * blockDim.x + threadIdx.x;
    if (i >= nidx) return;
    int r = idx[i];
    g_keep[r] = 1;
    float4 z = make_float4(0.f, 0.f, 0.f, 0.f);
    float4* p = reinterpret_cast<float4*>(g_a2 + (size_t)r * HID);
#pragma unroll
    for (int t = 0; t < HID / 4; t++) p[t] = z;
}

// ---------------------------------------------------------------------------
// Dense GEMM: out[r][j] = sum_k A[r][k] * W[k][j] + b[j]
// SECOND=true: A = relu(g_a1)*mask, out = g_h3. SECOND=false: A = x, out = g_h1.
// blockDim = (64, 4); each block does 32 rows; each thread 8 rows x 1 col.
// ---------------------------------------------------------------------------
template <int K, bool SECOND>
__global__ void __launch_bounds__(256) k_gemm(const float* __restrict__ Aext,
                                              const float* __restrict__ W,
                                              const float* __restrict__ bias,
                                              const float* __restrict__ mask,
                                              int nrows) {
    __shared__ float Ws[K * HID];
    __shared__ float As[32 * K];

    const float* A = SECOND ? g_a1 : Aext;
    float* out = SECOND ? g_h3 : g_h1;

    int tid = threadIdx.y * 64 + threadIdx.x;

    // Stage W (K x 64) into smem
    for (int t = tid; t < K * HID / 4; t += 256)
        reinterpret_cast<float4*>(Ws)[t] =
            reinterpret_cast<const float4*>(W)[t];

    // Stage A tile (32 x K) into smem; fuse relu*mask for second layer
    int row0 = blockIdx.x * 32;
    const int vecs_per_row = K / 4;
    for (int t = tid; t < 32 * vecs_per_row; t += 256) {
        int r = row0 + t / vecs_per_row;
        int v = t % vecs_per_row;
        float4 a = make_float4(0.f, 0.f, 0.f, 0.f);
        if (r < nrows) {
            a = reinterpret_cast<const float4*>(A)[(size_t)r * vecs_per_row + v];
            if (SECOND) {
                float4 m = reinterpret_cast<const float4*>(mask)[(size_t)r * vecs_per_row + v];
                a.x = fmaxf(a.x, 0.f) * m.x;
                a.y = fmaxf(a.y, 0.f) * m.y;
                a.z = fmaxf(a.z, 0.f) * m.z;
                a.w = fmaxf(a.w, 0.f) * m.w;
            }
        }
        reinterpret_cast<float4*>(As)[t] = a;
    }
    __syncthreads();

    int j = threadIdx.x;   // output column 0..63
    float acc[8];
#pragma unroll
    for (int i = 0; i < 8; i++) acc[i] = 0.f;

#pragma unroll 4
    for (int k = 0; k < K; k++) {
        float w = Ws[k * HID + j];
#pragma unroll
        for (int i = 0; i < 8; i++)
            acc[i] += As[(threadIdx.y + 4 * i) * K + k] * w;
    }

    float bj = bias[j];
#pragma unroll
    for (int i = 0; i < 8; i++) {
        int r = row0 + threadIdx.y + 4 * i;
        if (r < nrows)
            out[(size_t)r * HID + j] = acc[i] + bj;
    }
}

// ---------------------------------------------------------------------------
// SpMM: dst[row[e]] += vals[e] * src[col[e]]. 16 lanes per edge, float4 each,
// vector red.global.add.v4.f32 scatter. SECOND=true filters by g_keep.
// ---------------------------------------------------------------------------
template <bool SECOND>
__global__ void __launch_bounds__(256) k_spmm(const float* __restrict__ vals,
                                              const int* __restrict__ row,
                                              const int* __restrict__ col,
                                              int E) {
    int g = blockIdx.x * blockDim.x + threadIdx.x;
    int e = g >> 4;
    if (e >= E) return;
    int lane = g & 15;

    int r = row[e];
    if (SECOND && !g_keep[r]) return;

    const float* src = SECOND ? g_h3 : g_h1;
    float* dst = SECOND ? g_a2 : g_a1;

    float v = __ldg(vals + e);
    int c = __ldg(col + e);

    float4 xv = __ldg(reinterpret_cast<const float4*>(src + (size_t)c * HID) + lane);
    float4 o;
    o.x = xv.x * v; o.y = xv.y * v; o.z = xv.z * v; o.w = xv.w * v;

    float* p = dst + (size_t)r * HID + lane * 4;
    asm volatile("red.global.add.v4.f32 [%0], {%1, %2, %3, %4};"
                 :: "l"(p), "f"(o.x), "f"(o.y), "f"(o.z), "f"(o.w)
                 : "memory");
}

// ---------------------------------------------------------------------------
// Gather: out[i] = a2[idx[i]]
// ---------------------------------------------------------------------------
__global__ void k_gather(const int* __restrict__ idx, float* __restrict__ out,
                         int nidx) {
    int t = blockIdx.x * blockDim.x + threadIdx.x;
    int total = nidx * (HID / 4);
    if (t >= total) return;
    int i = t / (HID / 4);
    int v = t % (HID / 4);
    int r = __ldg(idx + i);
    reinterpret_cast<float4*>(out)[t] =
        reinterpret_cast<const float4*>(g_a2 + (size_t)r * HID)[v];
}

// ---------------------------------------------------------------------------
extern "C" void kernel_launch(void* const* d_in, const int* in_sizes, int n_in,
                              void* d_out, int out_size) {
    const float* x    = (const float*)d_in[0];
    const float* vals = (const float*)d_in[1];
    const float* W1   = (const float*)d_in[2];
    const float* b1   = (const float*)d_in[3];
    const float* W2   = (const float*)d_in[4];
    const float* b2   = (const float*)d_in[5];
    const float* mask = (const float*)d_in[6];
    const int*   row  = (const int*)d_in[7];
    const int*   col  = (const int*)d_in[8];
    const int*   idx  = (const int*)d_in[9];

    int n    = in_sizes[0] / FEAT;   // 100000
    int E    = in_sizes[1];          // 1600000
    int nidx = in_sizes[9];          // 10000

    float* out = (float*)d_out;

    k_reset<<<1024, 256>>>(n);
    k_mark<<<(nidx + 255) / 256, 256>>>(idx, nidx);

    dim3 gblk(64, 4);
    k_gemm<FEAT, false><<<(n + 31) / 32, gblk>>>(x, W1, b1, nullptr, n);

    int spmm_blocks = (E * 16 + 255) / 256;
    k_spmm<false><<<spmm_blocks, 256>>>(vals, row, col, E);

    k_gemm<HID, true><<<(n + 31) / 32, gblk>>>(nullptr, W2, b2, mask, n);

    k_spmm<true><<<spmm_blocks, 256>>>(vals, row, col, E);

    k_gather<<<(nidx * (HID / 4) + 255) / 256, 256>>>(idx, out, nidx);
}

// round 2
// speedup vs baseline: 1.1842x; 1.1842x over previous
#include <cuda_runtime.h>
#include <cstdint>

#define FEAT 128
#define HID  64
#define NMAX 100000

// Scratch (device globals — no runtime allocation allowed)
__device__ float g_h1[NMAX * HID];   // x@W1+b1
__device__ float g_a1[NMAX * HID];   // spmm1 output
__device__ float g_h3[NMAX * HID];   // (relu(a1)*mask)@W2+b2
__device__ float g_a2[NMAX * HID];   // spmm2 output (only kept rows valid)
__device__ unsigned char g_keep[NMAX];

// ---------------------------------------------------------------------------
__global__ void k_reset(int n) {
    int tid = blockIdx.x * blockDim.x + threadIdx.x;
    int stride = gridDim.x * blockDim.x;
    int total4 = n * HID / 4;
    float4 z = make_float4(0.f, 0.f, 0.f, 0.f);
    for (int t = tid; t < total4; t += stride)
        reinterpret_cast<float4*>(g_a1)[t] = z;
    for (int t = tid; t < n; t += stride)
        g_keep[t] = 0;
}

__global__ void k_mark(const int* __restrict__ idx, int nidx) {
    int i = blockIdx.x * blockDim.x + threadIdx.x;
    if (i >= nidx) return;
    int r = idx[i];
    g_keep[r] = 1;
    float4 z = make_float4(0.f, 0.f, 0.f, 0.f);
    float4* p = reinterpret_cast<float4*>(g_a2 + (size_t)r * HID);
#pragma unroll
    for (int t = 0; t < HID / 4; t++) p[t] = z;
}

// ---------------------------------------------------------------------------
// GEMM with packed fma.rn.f32x2.
// Block tile: 64 rows x 64 cols, 256 threads.
// Thread tile: 2 rows x 8 cols (cols {4tx..4tx+3, 4tx+32..4tx+35}).
// K chunked by 32 into padded smem (stride 34 -> conflict-free A broadcast).
// ---------------------------------------------------------------------------
#define KCH 32
#define ASTRIDE (KCH + 2)

__device__ __forceinline__ void fma2(unsigned long long& acc,
                                     unsigned long long a,
                                     unsigned long long b) {
    asm("fma.rn.f32x2 %0, %1, %2, %0;" : "+l"(acc) : "l"(a), "l"(b));
}

template <int K, bool SECOND>
__global__ void __launch_bounds__(256) k_gemm(const float* __restrict__ Aext,
                                              const float* __restrict__ W,
                                              const float* __restrict__ bias,
                                              const float* __restrict__ mask,
                                              int nrows) {
    __shared__ float Ws[K * HID];          // up to 32 KB
    __shared__ float As[64 * ASTRIDE];     // 8.5 KB

    const float* A = SECOND ? g_a1 : Aext;
    float* out = SECOND ? g_h3 : g_h1;

    int tid = threadIdx.x;
    int tx = tid & 7;          // 8 col groups
    int ty = tid >> 3;         // 32 row groups (2 rows each)
    int row0 = blockIdx.x * 64;

    // Stage full W (K x 64) into smem
    for (int t = tid; t < K * HID / 4; t += 256)
        reinterpret_cast<float4*>(Ws)[t] =
            reinterpret_cast<const float4*>(W)[t];

    union F2 { unsigned long long u; float2 f; };
    F2 acc[2][4];
#pragma unroll
    for (int i = 0; i < 2; i++)
#pragma unroll
        for (int p = 0; p < 4; p++) acc[i][p].u = 0ull;

    const int vpr = K / 4;  // float4 vectors per source row

    for (int kc = 0; kc < K; kc += KCH) {
        __syncthreads();
        // Stage A chunk: 64 rows x 32 k (padded stride)
        for (int t = tid; t < 64 * (KCH / 4); t += 256) {
            int r = t >> 3;           // KCH/4 == 8
            int kv = t & 7;
            float4 a = make_float4(0.f, 0.f, 0.f, 0.f);
            int gr = row0 + r;
            if (gr < nrows) {
                a = reinterpret_cast<const float4*>(A)[(size_t)gr * vpr + (kc / 4) + kv];
                if (SECOND) {
                    float4 m = reinterpret_cast<const float4*>(mask)[(size_t)gr * vpr + (kc / 4) + kv];
                    a.x = fmaxf(a.x, 0.f) * m.x;
                    a.y = fmaxf(a.y, 0.f) * m.y;
                    a.z = fmaxf(a.z, 0.f) * m.z;
                    a.w = fmaxf(a.w, 0.f) * m.w;
                }
            }
            float2* p = reinterpret_cast<float2*>(&As[r * ASTRIDE + kv * 4]);
            p[0] = make_float2(a.x, a.y);
            p[1] = make_float2(a.z, a.w);
        }
        __syncthreads();

#pragma unroll 8
        for (int kk = 0; kk < KCH; kk++) {
            int k = kc + kk;
            ulonglong2 wlo = *reinterpret_cast<const ulonglong2*>(&Ws[k * HID + 4 * tx]);
            ulonglong2 whi = *reinterpret_cast<const ulonglong2*>(&Ws[k * HID + 4 * tx + 32]);
#pragma unroll
            for (int i = 0; i < 2; i++) {
                float a = As[(ty * 2 + i) * ASTRIDE + kk];
                unsigned long long aa;
                asm("mov.b64 %0, {%1, %1};" : "=l"(aa) : "f"(a));
                fma2(acc[i][0].u, aa, wlo.x);
                fma2(acc[i][1].u, aa, wlo.y);
                fma2(acc[i][2].u, aa, whi.x);
                fma2(acc[i][3].u, aa, whi.y);
            }
        }
    }

    float4 blo = *reinterpret_cast<const float4*>(bias + 4 * tx);
    float4 bhi = *reinterpret_cast<const float4*>(bias + 4 * tx + 32);
#pragma unroll
    for (int i = 0; i < 2; i++) {
        int r = row0 + ty * 2 + i;
        if (r >= nrows) continue;
        float4 olo, ohi;
        olo.x = acc[i][0].f.x + blo.x;  olo.y = acc[i][0].f.y + blo.y;
        olo.z = acc[i][1].f.x + blo.z;  olo.w = acc[i][1].f.y + blo.w;
        ohi.x = acc[i][2].f.x + bhi.x;  ohi.y = acc[i][2].f.y + bhi.y;
        ohi.z = acc[i][3].f.x + bhi.z;  ohi.w = acc[i][3].f.y + bhi.w;
        *reinterpret_cast<float4*>(&out[(size_t)r * HID + 4 * tx]) = olo;
        *reinterpret_cast<float4*>(&out[(size_t)r * HID + 4 * tx + 32]) = ohi;
    }
}

// ---------------------------------------------------------------------------
// SpMM with 4 edges per thread (MLP=4 on the random gathers).
// 16 lanes per edge, float4 per lane, red.global.add.v4.f32 scatter.
// ---------------------------------------------------------------------------
template <bool SECOND>
__global__ void __launch_bounds__(256) k_spmm(const float* __restrict__ vals,
                                              const int* __restrict__ row,
                                              const int* __restrict__ col,
                                              int E, int nslots) {
    int g = blockIdx.x * blockDim.x + threadIdx.x;
    int lane = g & 15;
    int s = g >> 4;

    const float* src = SECOND ? g_h3 : g_h1;
    float* dst = SECOND ? g_a2 : g_a1;

    int e[4], r[4], c[4];
    float v[4];
    bool ok[4];
#pragma unroll
    for (int j = 0; j < 4; j++) {
        e[j] = s + j * nslots;
        ok[j] = (e[j] < E);
        r[j] = 0; c[j] = 0; v[j] = 0.f;
        if (ok[j]) {
            r[j] = __ldg(row + e[j]);
            c[j] = __ldg(col + e[j]);
            v[j] = __ldg(vals + e[j]);
        }
    }
    if (SECOND) {
#pragma unroll
        for (int j = 0; j < 4; j++)
            if (ok[j]) ok[j] = (g_keep[r[j]] != 0);
    }

    float4 xv[4];
#pragma unroll
    for (int j = 0; j < 4; j++) {
        xv[j] = make_float4(0.f, 0.f, 0.f, 0.f);
        if (ok[j])
            xv[j] = __ldg(reinterpret_cast<const float4*>(src + (size_t)c[j] * HID) + lane);
    }

#pragma unroll
    for (int j = 0; j < 4; j++) {
        if (!ok[j]) continue;
        float4 o;
        o.x = xv[j].x * v[j]; o.y = xv[j].y * v[j];
        o.z = xv[j].z * v[j]; o.w = xv[j].w * v[j];
        float* p = dst + (size_t)r[j] * HID + lane * 4;
        asm volatile("red.global.add.v4.f32 [%0], {%1, %2, %3, %4};"
                     :: "l"(p), "f"(o.x), "f"(o.y), "f"(o.z), "f"(o.w)
                     : "memory");
    }
}

// ---------------------------------------------------------------------------
__global__ void k_gather(const int* __restrict__ idx, float* __restrict__ out,
                         int nidx) {
    int t = blockIdx.x * blockDim.x + threadIdx.x;
    int total = nidx * (HID / 4);
    if (t >= total) return;
    int i = t / (HID / 4);
    int v = t % (HID / 4);
    int r = __ldg(idx + i);
    reinterpret_cast<float4*>(out)[t] =
        reinterpret_cast<const float4*>(g_a2 + (size_t)r * HID)[v];
}

// ---------------------------------------------------------------------------
extern "C" void kernel_launch(void* const* d_in, const int* in_sizes, int n_in,
                              void* d_out, int out_size) {
    const float* x    = (const float*)d_in[0];
    const float* vals = (const float*)d_in[1];
    const float* W1   = (const float*)d_in[2];
    const float* b1   = (const float*)d_in[3];
    const float* W2   = (const float*)d_in[4];
    const float* b2   = (const float*)d_in[5];
    const float* mask = (const float*)d_in[6];
    const int*   row  = (const int*)d_in[7];
    const int*   col  = (const int*)d_in[8];
    const int*   idx  = (const int*)d_in[9];

    int n    = in_sizes[0] / FEAT;   // 100000
    int E    = in_sizes[1];          // 1600000
    int nidx = in_sizes[9];          // 10000

    float* out = (float*)d_out;

    k_reset<<<2048, 256>>>(n);
    k_mark<<<(nidx + 255) / 256, 256>>>(idx, nidx);

    k_gemm<FEAT, false><<<(n + 63) / 64, 256>>>(x, W1, b1, nullptr, n);

    int nslots = (E + 3) / 4;
    int spmm_blocks = (nslots * 16 + 255) / 256;
    k_spmm<false><<<spmm_blocks, 256>>>(vals, row, col, E, nslots);

    k_gemm<HID, true><<<(n + 63) / 64, 256>>>(nullptr, W2, b2, mask, n);

    k_spmm<true><<<spmm_blocks, 256>>>(vals, row, col, E, nslots);

    k_gather<<<(nidx * (HID / 4) + 255) / 256, 256>>>(idx, out, nidx);
}

// round 3
// speedup vs baseline: 1.5392x; 1.2999x over previous
#include <cuda_runtime.h>
#include <cstdint>

#define FEAT 128
#define HID  64
#define NMAX 100000
#define EMAX 1600000

// Scratch (device globals — no runtime allocation allowed)
__device__ float g_h1[NMAX * HID];        // x@W1+b1
__device__ float g_a1[NMAX * HID];        // spmm1 output (only needed rows valid)
__device__ float g_h3[NMAX * HID];        // (relu(a1)*mask)@W2+b2
__device__ int   g_counts[NMAX];          // row degree, then scan workspace
__device__ int   g_rowptr[NMAX + 1];      // CSR row pointers
__device__ int   g_cursor[NMAX];          // scatter cursors
__device__ int2  g_csr[EMAX];             // {col, val bits} sorted by row
__device__ int   g_blocksums[256];
__device__ unsigned char g_need[NMAX];    // node needed as spmm1 output row?

// ---------------------------------------------------------------------------
// Zero counts + need flags
// ---------------------------------------------------------------------------
__global__ void k_zero(int n) {
    int tid = blockIdx.x * blockDim.x + threadIdx.x;
    int stride = gridDim.x * blockDim.x;
    for (int t = tid; t < n; t += stride) {
        g_counts[t] = 0;
        g_need[t] = 0;
    }
}

// ---------------------------------------------------------------------------
// Degree count
// ---------------------------------------------------------------------------
__global__ void k_count(const int* __restrict__ row, int E) {
    int e = blockIdx.x * blockDim.x + threadIdx.x;
    if (e < E) atomicAdd(&g_counts[__ldg(row + e)], 1);
}

// ---------------------------------------------------------------------------
// Scan stage 1: per-block (1024 elems, 256 threads x 4) exclusive partials
// ---------------------------------------------------------------------------
__global__ void __launch_bounds__(256) k_scan1(int n) {
    __shared__ int ssum[256];
    int t = threadIdx.x;
    int base = blockIdx.x * 1024 + t * 4;
    int v[4], s = 0;
#pragma unroll
    for (int j = 0; j < 4; j++) {
        int i = base + j;
        v[j] = (i < n) ? g_counts[i] : 0;
        s += v[j];
    }
    ssum[t] = s;
    __syncthreads();
#pragma unroll
    for (int d = 1; d < 256; d <<= 1) {
        int add = (t >= d) ? ssum[t - d] : 0;
        __syncthreads();
        ssum[t] += add;
        __syncthreads();
    }
    int run = ssum[t] - s;   // exclusive prefix of this thread within block
#pragma unroll
    for (int j = 0; j < 4; j++) {
        int i = base + j;
        if (i < n) g_rowptr[i] = run;
        run += v[j];
    }
    if (t == 255) g_blocksums[blockIdx.x] = ssum[255];
}

// ---------------------------------------------------------------------------
// Scan stage 2: exclusive scan of block sums (nb <= 256)
// ---------------------------------------------------------------------------
__global__ void __launch_bounds__(256) k_scan2(int nb) {
    __shared__ int s[256];
    int t = threadIdx.x;
    int orig = (t < nb) ? g_blocksums[t] : 0;
    s[t] = orig;
    __syncthreads();
#pragma unroll
    for (int d = 1; d < 256; d <<= 1) {
        int add = (t >= d) ? s[t - d] : 0;
        __syncthreads();
        s[t] += add;
        __syncthreads();
    }
    if (t < nb) g_blocksums[t] = s[t] - orig;
}

// ---------------------------------------------------------------------------
// Scan stage 3: add block offsets, init cursors, cap rowptr
// ---------------------------------------------------------------------------
__global__ void k_scan3(int n, int E) {
    int i = blockIdx.x * blockDim.x + threadIdx.x;
    if (i < n) {
        int v = g_rowptr[i] + g_blocksums[i >> 10];
        g_rowptr[i] = v;
        g_cursor[i] = v;
    }
    if (i == 0) g_rowptr[n] = E;
}

// ---------------------------------------------------------------------------
// Scatter edges into CSR order
// ---------------------------------------------------------------------------
__global__ void k_scatter(const float* __restrict__ vals,
                          const int* __restrict__ row,
                          const int* __restrict__ col, int E) {
    int e = blockIdx.x * blockDim.x + threadIdx.x;
    if (e >= E) return;
    int r = __ldg(row + e);
    int pos = atomicAdd(&g_cursor[r], 1);
    g_csr[pos] = make_int2(__ldg(col + e), __float_as_int(__ldg(vals + e)));
}

// ---------------------------------------------------------------------------
// Mark nodes needed as spmm1 outputs: neighbors of rows in idx
// ---------------------------------------------------------------------------
__global__ void k_mark_need(const int* __restrict__ idx, int nidx) {
    int g = blockIdx.x * blockDim.x + threadIdx.x;
    int i = g >> 4;
    if (i >= nidx) return;
    int lane = g & 15;
    int r = __ldg(idx + i);
    int s = g_rowptr[r], eEnd = g_rowptr[r + 1];
    for (int e = s + lane; e < eEnd; e += 16)
        g_need[g_csr[e].x] = 1;
}

// ---------------------------------------------------------------------------
// GEMM with packed fma.rn.f32x2 (unchanged from R2).
// ---------------------------------------------------------------------------
#define KCH 32
#define ASTRIDE (KCH + 2)

__device__ __forceinline__ void fma2(unsigned long long& acc,
                                     unsigned long long a,
                                     unsigned long long b) {
    asm("fma.rn.f32x2 %0, %1, %2, %0;" : "+l"(acc) : "l"(a), "l"(b));
}

template <int K, bool SECOND>
__global__ void __launch_bounds__(256) k_gemm(const float* __restrict__ Aext,
                                              const float* __restrict__ W,
                                              const float* __restrict__ bias,
                                              const float* __restrict__ mask,
                                              int nrows) {
    __shared__ float Ws[K * HID];
    __shared__ float As[64 * ASTRIDE];

    const float* A = SECOND ? g_a1 : Aext;
    float* out = SECOND ? g_h3 : g_h1;

    int tid = threadIdx.x;
    int tx = tid & 7;
    int ty = tid >> 3;
    int row0 = blockIdx.x * 64;

    for (int t = tid; t < K * HID / 4; t += 256)
        reinterpret_cast<float4*>(Ws)[t] =
            reinterpret_cast<const float4*>(W)[t];

    union F2 { unsigned long long u; float2 f; };
    F2 acc[2][4];
#pragma unroll
    for (int i = 0; i < 2; i++)
#pragma unroll
        for (int p = 0; p < 4; p++) acc[i][p].u = 0ull;

    const int vpr = K / 4;

    for (int kc = 0; kc < K; kc += KCH) {
        __syncthreads();
        for (int t = tid; t < 64 * (KCH / 4); t += 256) {
            int r = t >> 3;
            int kv = t & 7;
            float4 a = make_float4(0.f, 0.f, 0.f, 0.f);
            int gr = row0 + r;
            if (gr < nrows) {
                a = reinterpret_cast<const float4*>(A)[(size_t)gr * vpr + (kc / 4) + kv];
                if (SECOND) {
                    float4 m = reinterpret_cast<const float4*>(mask)[(size_t)gr * vpr + (kc / 4) + kv];
                    a.x = fmaxf(a.x, 0.f) * m.x;
                    a.y = fmaxf(a.y, 0.f) * m.y;
                    a.z = fmaxf(a.z, 0.f) * m.z;
                    a.w = fmaxf(a.w, 0.f) * m.w;
                }
            }
            float2* p = reinterpret_cast<float2*>(&As[r * ASTRIDE + kv * 4]);
            p[0] = make_float2(a.x, a.y);
            p[1] = make_float2(a.z, a.w);
        }
        __syncthreads();

#pragma unroll 8
        for (int kk = 0; kk < KCH; kk++) {
            int k = kc + kk;
            ulonglong2 wlo = *reinterpret_cast<const ulonglong2*>(&Ws[k * HID + 4 * tx]);
            ulonglong2 whi = *reinterpret_cast<const ulonglong2*>(&Ws[k * HID + 4 * tx + 32]);
#pragma unroll
            for (int i = 0; i < 2; i++) {
                float a = As[(ty * 2 + i) * ASTRIDE + kk];
                unsigned long long aa;
                asm("mov.b64 %0, {%1, %1};" : "=l"(aa) : "f"(a));
                fma2(acc[i][0].u, aa, wlo.x);
                fma2(acc[i][1].u, aa, wlo.y);
                fma2(acc[i][2].u, aa, whi.x);
                fma2(acc[i][3].u, aa, whi.y);
            }
        }
    }

    float4 blo = *reinterpret_cast<const float4*>(bias + 4 * tx);
    float4 bhi = *reinterpret_cast<const float4*>(bias + 4 * tx + 32);
#pragma unroll
    for (int i = 0; i < 2; i++) {
        int r = row0 + ty * 2 + i;
        if (r >= nrows) continue;
        float4 olo, ohi;
        olo.x = acc[i][0].f.x + blo.x;  olo.y = acc[i][0].f.y + blo.y;
        olo.z = acc[i][1].f.x + blo.z;  olo.w = acc[i][1].f.y + blo.w;
        ohi.x = acc[i][2].f.x + bhi.x;  ohi.y = acc[i][2].f.y + bhi.y;
        ohi.z = acc[i][3].f.x + bhi.z;  ohi.w = acc[i][3].f.y + bhi.w;
        *reinterpret_cast<float4*>(&out[(size_t)r * HID + 4 * tx]) = olo;
        *reinterpret_cast<float4*>(&out[(size_t)r * HID + 4 * tx + 32]) = ohi;
    }
}

// ---------------------------------------------------------------------------
// CSR SpMM row body: 16 lanes per row, register accumulation, unroll-2.
// ---------------------------------------------------------------------------
__device__ __forceinline__ float4 csr_row_accum(const float* __restrict__ src,
                                                int s, int eEnd, int lane) {
    float4 acc = make_float4(0.f, 0.f, 0.f, 0.f);
    int e = s;
    for (; e + 1 < eEnd; e += 2) {
        int2 cv0 = __ldg(&g_csr[e]);
        int2 cv1 = __ldg(&g_csr[e + 1]);
        float4 x0 = __ldg(reinterpret_cast<const float4*>(src + (size_t)cv0.x * HID) + lane);
        float4 x1 = __ldg(reinterpret_cast<const float4*>(src + (size_t)cv1.x * HID) + lane);
        float v0 = __int_as_float(cv0.y);
        float v1 = __int_as_float(cv1.y);
        acc.x += v0 * x0.x + v1 * x1.x;
        acc.y += v0 * x0.y + v1 * x1.y;
        acc.z += v0 * x0.z + v1 * x1.z;
        acc.w += v0 * x0.w + v1 * x1.w;
    }
    if (e < eEnd) {
        int2 cv = __ldg(&g_csr[e]);
        float4 x = __ldg(reinterpret_cast<const float4*>(src + (size_t)cv.x * HID) + lane);
        float v = __int_as_float(cv.y);
        acc.x += v * x.x;  acc.y += v * x.y;
        acc.z += v * x.z;  acc.w += v * x.w;
    }
    return acc;
}

// SpMM1: a1[r] = sum over row r (only rows with g_need[r])
__global__ void __launch_bounds__(256) k_spmm1(int n) {
    int g = blockIdx.x * blockDim.x + threadIdx.x;
    int r = g >> 4;
    if (r >= n) return;
    if (!g_need[r]) return;
    int lane = g & 15;
    int s = g_rowptr[r], eEnd = g_rowptr[r + 1];
    float4 acc = csr_row_accum(g_h1, s, eEnd, lane);
    reinterpret_cast<float4*>(g_a1 + (size_t)r * HID)[lane] = acc;
}

// SpMM2: out[i] = sum over row idx[i], written straight to d_out
__global__ void __launch_bounds__(256) k_spmm2(const int* __restrict__ idx,
                                               float* __restrict__ out,
                                               int nidx) {
    int g = blockIdx.x * blockDim.x + threadIdx.x;
    int i = g >> 4;
    if (i >= nidx) return;
    int lane = g & 15;
    int r = __ldg(idx + i);
    int s = g_rowptr[r], eEnd = g_rowptr[r + 1];
    float4 acc = csr_row_accum(g_h3, s, eEnd, lane);
    reinterpret_cast<float4*>(out + (size_t)i * HID)[lane] = acc;
}

// ---------------------------------------------------------------------------
extern "C" void kernel_launch(void* const* d_in, const int* in_sizes, int n_in,
                              void* d_out, int out_size) {
    const float* x    = (const float*)d_in[0];
    const float* vals = (const float*)d_in[1];
    const float* W1   = (const float*)d_in[2];
    const float* b1   = (const float*)d_in[3];
    const float* W2   = (const float*)d_in[4];
    const float* b2   = (const float*)d_in[5];
    const float* mask = (const float*)d_in[6];
    const int*   row  = (const int*)d_in[7];
    const int*   col  = (const int*)d_in[8];
    const int*   idx  = (const int*)d_in[9];

    int n    = in_sizes[0] / FEAT;   // 100000
    int E    = in_sizes[1];          // 1600000
    int nidx = in_sizes[9];          // 10000

    float* out = (float*)d_out;

    int nb = (n + 1023) / 1024;      // scan blocks (98)

    // --- CSR build ---
    k_zero<<<256, 256>>>(n);
    k_count<<<(E + 255) / 256, 256>>>(row, E);
    k_scan1<<<nb, 256>>>(n);
    k_scan2<<<1, 256>>>(nb);
    k_scan3<<<(n + 255) / 256, 256>>>(n, E);
    k_scatter<<<(E + 255) / 256, 256>>>(vals, row, col, E);
    k_mark_need<<<(nidx * 16 + 255) / 256, 256>>>(idx, nidx);

    // --- GCN layers ---
    k_gemm<FEAT, false><<<(n + 63) / 64, 256>>>(x, W1, b1, nullptr, n);
    k_spmm1<<<(n * 16 + 255) / 256, 256>>>(n);
    k_gemm<HID, true><<<(n + 63) / 64, 256>>>(nullptr, W2, b2, mask, n);
    k_spmm2<<<(nidx * 16 + 255) / 256, 256>>>(idx, out, nidx);
}